// round 14
// baseline (speedup 1.0000x reference)
#include <cuda_runtime.h>
#include <cuda_pipeline.h>

typedef unsigned long long ull;

// Problem dims
#define NC_  31
#define NXL  256
#define NYL  256
#define NO_  3
#define KXL  17
#define KYL  17
#define NG_  (NO_ * NC_)   // 93
#define WIN_ 9

// Compact weights: per (o,c) group a 9x9 tile of broadcast (v,v) float2 pairs
__device__ float2 g_w2[NG_ * 81];
__device__ int    g_ori[NG_];   // (kx0 << 8) | ky0

// ---------------------------------------------------------------------------
// Fused prep: one warp per group (origin via shfl-min, then scatter).
// ---------------------------------------------------------------------------
__global__ void prep_all(const float* __restrict__ vk,
                         const int* __restrict__ loc) {
    int w    = (blockIdx.x * blockDim.x + threadIdx.x) >> 5;
    int lane = threadIdx.x & 31;
    if (w >= NG_) return;

    int kxm = 1 << 30, kym = 1 << 30;
    int idxs[3]; float vs[3];
#pragma unroll
    for (int s = 0; s < 3; ++s) {
        int t = lane + 32 * s;
        if (t < 81) {
            int idx = loc[w * 81 + t];
            idxs[s] = idx;
            vs[s]   = vk[w * 81 + t];
            int ky = idx % KYL;
            int kx = (idx / KYL) % KXL;
            kxm = min(kxm, kx);
            kym = min(kym, ky);
        }
    }
#pragma unroll
    for (int off = 16; off; off >>= 1) {
        kxm = min(kxm, __shfl_xor_sync(0xffffffffu, kxm, off));
        kym = min(kym, __shfl_xor_sync(0xffffffffu, kym, off));
    }
    if (lane == 0) g_ori[w] = (kxm << 8) | kym;

#pragma unroll
    for (int s = 0; s < 3; ++s) {
        int t = lane + 32 * s;
        if (t < 81) {
            int idx = idxs[s];
            float v = fmaxf(vs[s], 0.0f);
            int ky = idx % KYL;
            int kx = (idx / KYL) % KXL;
            g_w2[w * 81 + (kx - kxm) * WIN_ + (ky - kym)] = make_float2(v, v);
        }
    }
}

// ---------------------------------------------------------------------------
// Main conv: 512-thread blocks, 2 blocks/SM (64-reg budget), 32 warps/SM.
// Thread = 1 output row x 8 cols (txc = tid&15 col group, tyr = tid>>4 row).
// Tile 32x128 per block, same 8B-aligned cp.async staging (16 threads/row),
// XOR-swizzled LDS.128 operands (4 units/thread both parities), dual-phase
// packed fma.rn.f32x2 (accA aligned 4 pairs, accB shifted 5 pairs; edge
// halves of accB discarded at merge). Weight pairs loaded just-in-time
// (<=2 pairs live) to hold the 64-register cap.
// ---------------------------------------------------------------------------
#define TH 32
#define TW 128
#define SRO 40                 // staged rows (TH + 8)
#define SWF 160                // smem row stride in floats
#define ROWB (SWF * 4)         // 640 bytes
#define TILE_B (SRO * ROWB)    // 25600 bytes
#define WPAD 10                // weight row stride in ull
#define WBUF (WIN_ * WPAD)     // 90 ull
#define SMEM_BYTES (2 * TILE_B + 2 * WBUF * 8 + NC_ * 4)  // 52764

#define FMA2(acc, a, b) \
    asm("fma.rn.f32x2 %0, %1, %2, %0;" : "+l"(acc) : "l"(a), "l"(b))

__device__ __forceinline__ int swz_unit(int cu) {
    return cu ^ ((cu >> 3) & 7);
}

__device__ __forceinline__ void ldE(const char* p, ull& a, ull& b) {
    longlong2 L = *(const longlong2*)p;
    a = (ull)L.x; b = (ull)L.y;
}

// GA: 4 aligned pairs t..t+3 ; GB: 5 shifted pairs t..t+4
#define GA(P, t, w) do { \
    FMA2(accA[0], P[(t)], w);   FMA2(accA[1], P[(t)+1], w); \
    FMA2(accA[2], P[(t)+2], w); FMA2(accA[3], P[(t)+3], w); } while (0)
#define GB(P, t, w) do { \
    FMA2(accB[0], P[(t)], w);   FMA2(accB[1], P[(t)+1], w); \
    FMA2(accB[2], P[(t)+2], w); FMA2(accB[3], P[(t)+3], w); \
    FMA2(accB[4], P[(t)+4], w); } while (0)

// One channel, parity SV = ky0 & 1.
// SV0 taps: A0 B0 A1 B1 A2 B2 A3 B3 A4 (tap v=2t -> GA t, v=2t+1 -> GB t)
// SV1 taps: B0 A1 B1 A2 B2 A3 B3 A4 B4 (tap v=2t -> GB t, v=2t+1 -> GA t+1)
template<int SV>
__device__ __forceinline__ void channel_math(
        const char* __restrict__ tb, const char* __restrict__ wb,
        const int* offs, ull* accA, ull* accB) {
    ull P[9];
#pragma unroll
    for (int e = 0; e < 4; ++e)
        ldE(tb + offs[e], P[2 * e], P[2 * e + 1]);
    if (SV == 1) { P[8] = *(const ull*)(tb + offs[4]); }

#pragma unroll
    for (int u = 0; u < 9; ++u) {
        const char* wr = wb + u * 80;
        const int rn = (u + 1) * ROWB;
        ull w0, w1;

        ldE(wr, w0, w1);
        if (SV == 0) { GA(P, 0, w0); GB(P, 0, w1); }
        else         { GB(P, 0, w0); GA(P, 1, w1); }

        ldE(wr + 16, w0, w1);
        if (SV == 0) { GA(P, 1, w0); GB(P, 1, w1); }
        else         { GB(P, 1, w0); GA(P, 2, w1); }

        if (u < 8) { ldE(tb + offs[0] + rn, P[0], P[1]); }   // unit0 next row

        ldE(wr + 32, w0, w1);
        if (SV == 0) { GA(P, 2, w0); GB(P, 2, w1); }
        else         { GB(P, 2, w0); GA(P, 3, w1); }

        ldE(wr + 48, w0, w1);
        if (SV == 0) { GA(P, 3, w0); GB(P, 3, w1); }
        else         { GB(P, 3, w0); GA(P, 4, w1); }

        if (u < 8) { ldE(tb + offs[1] + rn, P[2], P[3]); }   // unit1 next row

        w0 = *(const ull*)(wr + 64);
        if (SV == 0) { GA(P, 4, w0); }
        else         { GB(P, 4, w0); }

        if (u < 8) {                                         // units 2,3 (+P8)
            ldE(tb + offs[2] + rn, P[4], P[5]);
            ldE(tb + offs[3] + rn, P[6], P[7]);
            if (SV == 1) { P[8] = *(const ull*)(tb + offs[4] + rn); }
        }
    }
}

__global__ void __launch_bounds__(512, 2) conv_kernel(
        const float* __restrict__ x, float* __restrict__ out) {
    extern __shared__ float smem[];
    char* buf0 = (char*)smem;
    char* buf1 = buf0 + TILE_B;
    char* wb0  = buf1 + TILE_B;
    char* wb1  = wb0 + WBUF * 8;
    int*  s_ori = (int*)(wb1 + WBUF * 8);

    const int tid = threadIdx.x;
    const int t16 = tid & 15;         // 16 threads per staged row / col group
    const int tyr = tid >> 4;         // output row 0..31
    const int txc = t16;              // 8-col group (cols 8*txc .. 8*txc+7)

    const int o  = blockIdx.y;
    const int b  = blockIdx.z;
    const int i0 = (blockIdx.x >> 1) * TH;
    const int j0 = (blockIdx.x & 1) * TW;

    if (tid < NC_) { s_ori[tid] = g_ori[o * NC_ + tid]; }
    __syncthreads();

    const float* __restrict__ xb = x + (size_t)b * NC_ * NXL * NYL;
    const int wdoff = ((tid / WIN_) * WPAD + tid % WIN_) * 8;
    const int half8 = (t16 & 1) * 8;
    const int thcu  = t16 >> 1;       // 0..7

    // ---- 8B cp.async staging, 16 threads per row, 40 rows ----
    auto stage = [&](int c, char* tbuf, char* wbuf) {
        const int ori = s_ori[c];
        const int kx0 = ori >> 8, ky0 = ori & 255;
        const int A   = j0 + (ky0 & ~1) - 8;   // even, 8B-aligned gmem origin
        const int ri0 = i0 + kx0 - 8;
        const float* __restrict__ xc = xb + (size_t)c * (NXL * NYL);
#pragma unroll
        for (int pass = 0; pass < 2; ++pass) {
            if (pass == 1 && tyr >= 8) break;
            const int r  = tyr + pass * 32;
            const int gi = ri0 + r;
            const bool rowok = (unsigned)gi < NXL;
            const float* grow = xc + (rowok ? gi : 0) * NYL;
            char* rb = tbuf + r * ROWB;
#pragma unroll
            for (int m = 0; m < 4; ++m) {
                const int gcol = A + 2 * (t16 + 16 * m);
                const bool ok  = rowok && ((unsigned)gcol < NYL);
                const int dst  = swz_unit(thcu + 8 * m) * 16 + half8;
                __pipeline_memcpy_async(rb + dst,
                                        ok ? grow + gcol : (const float*)xc,
                                        8, ok ? 0 : 8);
            }
            if (t16 < 6) {   // tail: dword pairs 64..69 (units 32..34)
                const int gcol = A + 2 * (t16 + 64);
                const bool ok  = rowok && ((unsigned)gcol < NYL);
                const int dst  = swz_unit(32 + thcu) * 16 + half8;
                __pipeline_memcpy_async(rb + dst,
                                        ok ? grow + gcol : (const float*)xc,
                                        8, ok ? 0 : 8);
            }
        }
        if (tid < 81) {
            __pipeline_memcpy_async(wbuf + wdoff,
                                    ((const ull*)g_w2)
                                        + (size_t)(o * NC_ + c) * 81 + tid,
                                    8);
        }
        __pipeline_commit();
    };

    // per-thread swizzled E unit byte offsets (row-independent)
    int offs[5];
#pragma unroll
    for (int e = 0; e < 5; ++e)
        offs[e] = tyr * ROWB + swz_unit(2 * txc + e) * 16;

    ull accA[4], accB[5];
#pragma unroll
    for (int j = 0; j < 4; ++j) { accA[j] = 0ull; }
#pragma unroll
    for (int i = 0; i < 5; ++i) { accB[i] = 0ull; }

    stage(0, buf0, wb0);
    __pipeline_wait_prior(0);
    __syncthreads();

    for (int c = 0; c < NC_; ++c) {
        if (c + 1 < NC_)
            stage(c + 1, (c & 1) ? buf0 : buf1, (c & 1) ? wb0 : wb1);

        const char* tb = (c & 1) ? buf1 : buf0;
        const char* wb = (c & 1) ? wb1 : wb0;

        if (s_ori[c] & 1) { channel_math<1>(tb, wb, offs, accA, accB); }
        else              { channel_math<0>(tb, wb, offs, accA, accB); }

        __pipeline_wait_prior(0);
        __syncthreads();
    }

    // ---- epilogue: merge dual-phase accumulators, write 8 cols ----
    float res[8];
#pragma unroll
    for (int j = 0; j < 4; ++j) {
        res[2 * j]     = __uint_as_float((unsigned)(accA[j] & 0xffffffffull))
                       + __uint_as_float((unsigned)(accB[j] >> 32));
        res[2 * j + 1] = __uint_as_float((unsigned)(accA[j] >> 32))
                       + __uint_as_float((unsigned)(accB[j + 1] & 0xffffffffull));
    }
    float* op = out + ((size_t)(b * NO_ + o) * NXL + (i0 + tyr)) * NYL
                    + j0 + txc * 8;
    reinterpret_cast<float4*>(op)[0] = make_float4(res[0], res[1], res[2], res[3]);
    reinterpret_cast<float4*>(op)[1] = make_float4(res[4], res[5], res[6], res[7]);
}

// ---------------------------------------------------------------------------
extern "C" void kernel_launch(void* const* d_in, const int* in_sizes, int n_in,
                              void* d_out, int out_size) {
    const float* x   = (const float*)d_in[0];
    const float* vk  = (const float*)d_in[1];
    const int*   loc = (const int*)d_in[2];
    float* out = (float*)d_out;

    cudaFuncSetAttribute(conv_kernel,
                         cudaFuncAttributeMaxDynamicSharedMemorySize,
                         SMEM_BYTES);

    prep_all<<<(NG_ * 32 + 255) / 256, 256>>>(vk, loc);

    dim3 grid((NXL / TH) * (NYL / TW), NO_, 16);  // (16, 3, 16)
    conv_kernel<<<grid, 512, SMEM_BYTES>>>(x, out);
}

// round 15
// speedup vs baseline: 1.2563x; 1.2563x over previous
#include <cuda_runtime.h>
#include <cuda_pipeline.h>

typedef unsigned long long ull;

// Problem dims
#define NC_  31
#define NXL  256
#define NYL  256
#define NO_  3
#define KXL  17
#define KYL  17
#define NG_  (NO_ * NC_)   // 93
#define WIN_ 9

// Compact weights: per (o,c) group a 9x9 tile of broadcast (v,v) float2 pairs
__device__ float2 g_w2[NG_ * 81];
__device__ int    g_ori[NG_];   // (kx0 << 8) | ky0

// ---------------------------------------------------------------------------
// Fused prep: one warp per group (origin via shfl-min, then scatter).
// ---------------------------------------------------------------------------
__global__ void prep_all(const float* __restrict__ vk,
                         const int* __restrict__ loc) {
    int w    = (blockIdx.x * blockDim.x + threadIdx.x) >> 5;
    int lane = threadIdx.x & 31;
    if (w >= NG_) return;

    int kxm = 1 << 30, kym = 1 << 30;
    int idxs[3]; float vs[3];
#pragma unroll
    for (int s = 0; s < 3; ++s) {
        int t = lane + 32 * s;
        if (t < 81) {
            int idx = loc[w * 81 + t];
            idxs[s] = idx;
            vs[s]   = vk[w * 81 + t];
            int ky = idx % KYL;
            int kx = (idx / KYL) % KXL;
            kxm = min(kxm, kx);
            kym = min(kym, ky);
        }
    }
#pragma unroll
    for (int off = 16; off; off >>= 1) {
        kxm = min(kxm, __shfl_xor_sync(0xffffffffu, kxm, off));
        kym = min(kym, __shfl_xor_sync(0xffffffffu, kym, off));
    }
    if (lane == 0) g_ori[w] = (kxm << 8) | kym;

#pragma unroll
    for (int s = 0; s < 3; ++s) {
        int t = lane + 32 * s;
        if (t < 81) {
            int idx = idxs[s];
            float v = fmaxf(vs[s], 0.0f);
            int ky = idx % KYL;
            int kx = (idx / KYL) % KXL;
            g_w2[w * 81 + (kx - kxm) * WIN_ + (ky - kym)] = make_float2(v, v);
        }
    }
}

// ---------------------------------------------------------------------------
// Main conv: r9 math core, block split into TWO independent 128-thread
// pipelines (half h owns output rows 16h..16h+15 of the 32x128 tile).
// Each half: private 24-row double-buffered stage, private weight buffers,
// private named barrier (bar.sync 1+h, 128). The halves drift independently
// so one half's per-channel LDS burst overlaps the other half's FMA phase.
// Math per channel: 8B-aligned cp.async staging (parity absorbed by
// dual-phase fma.rn.f32x2 accumulators), XOR-swizzled LDS.128 operands with
// in-place register pipelining (r9 schedule, unchanged).
// ---------------------------------------------------------------------------
#define TH 32
#define TW 128
#define HROWS 24               // staged rows per half (16 out + 8 halo)
#define SWF 160                // smem row stride in floats
#define ROWB (SWF * 4)         // 640 bytes
#define HBUF (HROWS * ROWB)    // 15360 bytes per half-buffer
#define WPAD 10                // weight row stride in ull
#define WBUF 90                // ull per weight buffer
#define SMEM_BYTES (4 * HBUF + 4 * WBUF * 8 + NC_ * 4 + 128)  // ~64.5KB

#define FMA2(acc, a, b) \
    asm("fma.rn.f32x2 %0, %1, %2, %0;" : "+l"(acc) : "l"(a), "l"(b))

__device__ __forceinline__ int swz_unit(int cu) {
    return cu ^ ((cu >> 3) & 7);
}

__device__ __forceinline__ void ldE(const char* p, ull& a, ull& b) {
    longlong2 L = *(const longlong2*)p;
    a = (ull)L.x; b = (ull)L.y;
}

__device__ __forceinline__ void fmaA(ull* acc, const ull* p, ull w) {
#pragma unroll
    for (int j = 0; j < 8; ++j) FMA2(acc[j], p[j], w);
}
__device__ __forceinline__ void fmaB(ull* acc, const ull* p, ull w) {
#pragma unroll
    for (int i = 0; i < 9; ++i) FMA2(acc[i], p[i], w);
}

// Channel math, parity SV = ky0 & 1 (r9 core, unchanged).
template<int SV>
__device__ __forceinline__ void channel_math(
        const char* __restrict__ tb, const char* __restrict__ wb,
        const int* offs, ull* accA, ull* accB) {
    ull P[14];
#pragma unroll
    for (int e = 0; e < (SV ? 7 : 6); ++e)
        ldE(tb + offs[e], P[2 * e], P[2 * e + 1]);
    ull wp0, wp1;
    ldE(wb, wp0, wp1);                        // taps 0,1 of u=0

#pragma unroll
    for (int u = 0; u < 9; ++u) {
        const char* wr = wb + u * 80;
        const int rn = (u + 1) * ROWB;
        ull w2, w3, w4, w5, w6, w7;
        ldE(wr + 16, w2, w3);

        if (SV == 0) { fmaA(accA, P + 0, wp0); fmaB(accB, P + 0, wp1); }
        else         { fmaB(accB, P + 0, wp0); fmaA(accA, P + 1, wp1); }

        ldE(wr + 32, w4, w5);
        ldE(wr + 48, w6, w7);
        const ull w8 = *(const ull*)(wr + 64);

        if (SV == 0) { fmaA(accA, P + 1, w2); fmaB(accB, P + 1, w3); }
        else         { fmaB(accB, P + 1, w2); fmaA(accA, P + 2, w3); }

        if (u < 8) { ldE(tb + offs[0] + rn, P[0], P[1]); }   // unit0 next row

        if (SV == 0) { fmaA(accA, P + 2, w4); fmaB(accB, P + 2, w5); }
        else         { fmaB(accB, P + 2, w4); fmaA(accA, P + 3, w5); }

        if (SV == 0) { fmaA(accA, P + 3, w6); fmaB(accB, P + 3, w7); }
        else         { fmaB(accB, P + 3, w6); fmaA(accA, P + 4, w7); }

        if (u < 8) {
            ldE(tb + offs[1] + rn, P[2], P[3]);              // unit1 next row
            ldE(wr + 80, wp0, wp1);                          // taps 0,1 of u+1
        }

        if (SV == 0) { fmaA(accA, P + 4, w8); }
        else         { fmaB(accB, P + 4, w8); }

        if (u < 8) {                                         // units 2..5(6)
            ldE(tb + offs[2] + rn, P[4],  P[5]);
            ldE(tb + offs[3] + rn, P[6],  P[7]);
            ldE(tb + offs[4] + rn, P[8],  P[9]);
            ldE(tb + offs[5] + rn, P[10], P[11]);
            if (SV == 1) { ldE(tb + offs[6] + rn, P[12], P[13]); }
        }
    }
}

__global__ void __launch_bounds__(256, 3) conv_kernel(
        const float* __restrict__ x, float* __restrict__ out) {
    extern __shared__ float smem[];
    char* base  = (char*)smem;
    char* wbase = base + 4 * HBUF;
    int*  s_ori = (int*)(wbase + 4 * WBUF * 8);

    const int tid = threadIdx.x;
    const int h   = tid >> 7;          // half 0/1
    const int tl  = tid & 127;         // thread within half
    const int tx  = tl & 7;            // 16-col group
    const int tyl = tl >> 3;           // local output row 0..15

    // half-private buffers
    char* buf0 = base + h * (2 * HBUF);
    char* buf1 = buf0 + HBUF;
    char* wb0  = wbase + (2 * h) * (WBUF * 8);
    char* wb1  = wb0 + WBUF * 8;

    const int o  = blockIdx.y;
    const int b  = blockIdx.z;
    const int i0 = (blockIdx.x >> 1) * TH + 16 * h;  // this half's row base
    const int j0 = (blockIdx.x & 1) * TW;

    if (tid < NC_) { s_ori[tid] = g_ori[o * NC_ + tid]; }
    __syncthreads();   // only full-block sync; halves run free afterwards

    const float* __restrict__ xb = x + (size_t)b * NC_ * NXL * NYL;
    const int wdoff = ((tl / WIN_) * WPAD + tl % WIN_) * 8;
    const int half8 = (tx & 1) * 8;
    const int thcu  = tx >> 1;

    // ---- 8B cp.async staging of this half's 24 rows ----
    auto stage = [&](int c, char* tbuf, char* wbuf) {
        const int ori = s_ori[c];
        const int kx0 = ori >> 8, ky0 = ori & 255;
        const int A   = j0 + (ky0 & ~1) - 8;   // even, 8B-aligned gmem origin
        const int ri0 = i0 + kx0 - 8;
        const float* __restrict__ xc = xb + (size_t)c * (NXL * NYL);
#pragma unroll
        for (int pass = 0; pass < 2; ++pass) {
            if (pass == 1 && tyl >= 8) break;
            const int r  = tyl + pass * 16;    // 0..23
            const int gi = ri0 + r;
            const bool rowok = (unsigned)gi < NXL;
            const float* grow = xc + (rowok ? gi : 0) * NYL;
            char* rb = tbuf + r * ROWB;
#pragma unroll
            for (int m = 0; m < 8; ++m) {
                const int gcol = A + 2 * (tx + 8 * m);
                const bool ok  = rowok && ((unsigned)gcol < NYL);
                const int dst  = swz_unit(thcu + 4 * m) * 16 + half8;
                __pipeline_memcpy_async(rb + dst,
                                        ok ? grow + gcol : (const float*)xc,
                                        8, ok ? 0 : 8);
            }
            if (tx < 6) {   // tail: dword pairs 64..69 (units 32..34)
                const int gcol = A + 2 * (tx + 64);
                const bool ok  = rowok && ((unsigned)gcol < NYL);
                const int dst  = swz_unit(thcu + 32) * 16 + half8;
                __pipeline_memcpy_async(rb + dst,
                                        ok ? grow + gcol : (const float*)xc,
                                        8, ok ? 0 : 8);
            }
        }
        if (tl < 81) {
            __pipeline_memcpy_async(wbuf + wdoff,
                                    ((const ull*)g_w2)
                                        + (size_t)(o * NC_ + c) * 81 + tl,
                                    8);
        }
        __pipeline_commit();
    };

    // half-private barrier
    auto hbar = [&]() {
        asm volatile("bar.sync %0, %1;" :: "r"(1 + h), "r"(128) : "memory");
    };

    // per-thread swizzled E unit byte offsets (row-independent)
    int offs[7];
#pragma unroll
    for (int e = 0; e < 7; ++e)
        offs[e] = tyl * ROWB + swz_unit(4 * tx + e) * 16;

    ull accA[8], accB[9];
#pragma unroll
    for (int j = 0; j < 8; ++j) { accA[j] = 0ull; }
#pragma unroll
    for (int i = 0; i < 9; ++i) { accB[i] = 0ull; }

    stage(0, buf0, wb0);
    __pipeline_wait_prior(0);
    hbar();

    for (int c = 0; c < NC_; ++c) {
        if (c + 1 < NC_)
            stage(c + 1, (c & 1) ? buf0 : buf1, (c & 1) ? wb0 : wb1);

        const char* tb = (c & 1) ? buf1 : buf0;
        const char* wb = (c & 1) ? wb1 : wb0;

        if (s_ori[c] & 1) { channel_math<1>(tb, wb, offs, accA, accB); }
        else              { channel_math<0>(tb, wb, offs, accA, accB); }

        __pipeline_wait_prior(0);
        hbar();
    }

    // ---- epilogue: merge dual-phase accumulators, write 16 cols ----
    float res[16];
#pragma unroll
    for (int j = 0; j < 8; ++j) {
        float aLo = __uint_as_float((unsigned)(accA[j] & 0xffffffffull));
        float aHi = __uint_as_float((unsigned)(accA[j] >> 32));
        float bHi = __uint_as_float((unsigned)(accB[j] >> 32));
        float bLo = __uint_as_float((unsigned)(accB[j + 1] & 0xffffffffull));
        res[2 * j]     = aLo + bHi;
        res[2 * j + 1] = aHi + bLo;
    }
    float* op = out + ((size_t)(b * NO_ + o) * NXL + (i0 + tyl)) * NYL
                    + j0 + tx * 16;
#pragma unroll
    for (int q = 0; q < 4; ++q)
        reinterpret_cast<float4*>(op)[q] =
            make_float4(res[4 * q], res[4 * q + 1],
                        res[4 * q + 2], res[4 * q + 3]);
}

// ---------------------------------------------------------------------------
extern "C" void kernel_launch(void* const* d_in, const int* in_sizes, int n_in,
                              void* d_out, int out_size) {
    const float* x   = (const float*)d_in[0];
    const float* vk  = (const float*)d_in[1];
    const int*   loc = (const int*)d_in[2];
    float* out = (float*)d_out;

    cudaFuncSetAttribute(conv_kernel,
                         cudaFuncAttributeMaxDynamicSharedMemorySize,
                         SMEM_BYTES);

    prep_all<<<(NG_ * 32 + 255) / 256, 256>>>(vk, loc);

    dim3 grid((NXL / TH) * (NYL / TW), NO_, 16);  // (16, 3, 16)
    conv_kernel<<<grid, 256, SMEM_BYTES>>>(x, out);
}

// round 16
// speedup vs baseline: 1.3760x; 1.0953x over previous
#include <cuda_runtime.h>
#include <cuda_pipeline.h>

typedef unsigned long long ull;

// Problem dims
#define NC_  31
#define NXL  256
#define NYL  256
#define NO_  3
#define KXL  17
#define KYL  17
#define NG_  (NO_ * NC_)   // 93
#define WIN_ 9
#define NCHUNK 4           // channel chunks per spatial tile (8+8+8+7)

// Compact weights: per (o,c) group a 9x9 tile of broadcast (v,v) float2 pairs
__device__ float2 g_w2[NG_ * 81];
__device__ int    g_ori[NG_];   // (kx0 << 8) | ky0

// ---------------------------------------------------------------------------
// Zero-init the output (harness poisons it; we accumulate with atomics).
// ---------------------------------------------------------------------------
__global__ void zero_out(float4* __restrict__ out, int n4) {
    int i = blockIdx.x * blockDim.x + threadIdx.x;
    if (i < n4) out[i] = make_float4(0.f, 0.f, 0.f, 0.f);
}

// ---------------------------------------------------------------------------
// Fused prep: one warp per group (origin via shfl-min, then scatter).
// ---------------------------------------------------------------------------
__global__ void prep_all(const float* __restrict__ vk,
                         const int* __restrict__ loc) {
    int w    = (blockIdx.x * blockDim.x + threadIdx.x) >> 5;
    int lane = threadIdx.x & 31;
    if (w >= NG_) return;

    int kxm = 1 << 30, kym = 1 << 30;
    int idxs[3]; float vs[3];
#pragma unroll
    for (int s = 0; s < 3; ++s) {
        int t = lane + 32 * s;
        if (t < 81) {
            int idx = loc[w * 81 + t];
            idxs[s] = idx;
            vs[s]   = vk[w * 81 + t];
            int ky = idx % KYL;
            int kx = (idx / KYL) % KXL;
            kxm = min(kxm, kx);
            kym = min(kym, ky);
        }
    }
#pragma unroll
    for (int off = 16; off; off >>= 1) {
        kxm = min(kxm, __shfl_xor_sync(0xffffffffu, kxm, off));
        kym = min(kym, __shfl_xor_sync(0xffffffffu, kym, off));
    }
    if (lane == 0) g_ori[w] = (kxm << 8) | kym;

#pragma unroll
    for (int s = 0; s < 3; ++s) {
        int t = lane + 32 * s;
        if (t < 81) {
            int idx = idxs[s];
            float v = fmaxf(vs[s], 0.0f);
            int ky = idx % KYL;
            int kx = (idx / KYL) % KXL;
            g_w2[w * 81 + (kx - kxm) * WIN_ + (ky - kym)] = make_float2(v, v);
        }
    }
}

// ---------------------------------------------------------------------------
// Main conv: r9 math core exactly; each block handles ONE channel chunk of
// a 32x128 output tile (T = 3072 blocks -> 6.92 waves at 444 concurrent,
// 98.8% packing vs 86.5% for T=768). Partial sums merged into the
// zero-initialized output with red.global.add.f32.
// ---------------------------------------------------------------------------
#define TH 32
#define TW 128
#define SRO 40                 // staged rows (TH + 8)
#define SWF 160                // smem row stride in floats
#define ROWB (SWF * 4)         // 640 bytes
#define TILE_B (SRO * ROWB)    // 25600 bytes
#define WPAD 10                // weight row stride in ull
#define WBUF (WIN_ * WPAD)     // 90 ull
#define SMEM_BYTES (2 * TILE_B + 2 * WBUF * 8 + NC_ * 4)  // 52764

#define FMA2(acc, a, b) \
    asm("fma.rn.f32x2 %0, %1, %2, %0;" : "+l"(acc) : "l"(a), "l"(b))

__device__ __forceinline__ int swz_unit(int cu) {
    return cu ^ ((cu >> 3) & 7);
}

__device__ __forceinline__ void ldE(const char* p, ull& a, ull& b) {
    longlong2 L = *(const longlong2*)p;
    a = (ull)L.x; b = (ull)L.y;
}

__device__ __forceinline__ void fmaA(ull* acc, const ull* p, ull w) {
#pragma unroll
    for (int j = 0; j < 8; ++j) FMA2(acc[j], p[j], w);
}
__device__ __forceinline__ void fmaB(ull* acc, const ull* p, ull w) {
#pragma unroll
    for (int i = 0; i < 9; ++i) FMA2(acc[i], p[i], w);
}

// Channel math, parity SV = ky0 & 1 (r9 core, unchanged).
template<int SV>
__device__ __forceinline__ void channel_math(
        const char* __restrict__ tb, const char* __restrict__ wb,
        const int* offs, ull* accA, ull* accB) {
    ull P[14];
#pragma unroll
    for (int e = 0; e < (SV ? 7 : 6); ++e)
        ldE(tb + offs[e], P[2 * e], P[2 * e + 1]);
    ull wp0, wp1;
    ldE(wb, wp0, wp1);                        // taps 0,1 of u=0

#pragma unroll
    for (int u = 0; u < 9; ++u) {
        const char* wr = wb + u * 80;
        const int rn = (u + 1) * ROWB;
        ull w2, w3, w4, w5, w6, w7;
        ldE(wr + 16, w2, w3);

        if (SV == 0) { fmaA(accA, P + 0, wp0); fmaB(accB, P + 0, wp1); }
        else         { fmaB(accB, P + 0, wp0); fmaA(accA, P + 1, wp1); }

        ldE(wr + 32, w4, w5);
        ldE(wr + 48, w6, w7);
        const ull w8 = *(const ull*)(wr + 64);

        if (SV == 0) { fmaA(accA, P + 1, w2); fmaB(accB, P + 1, w3); }
        else         { fmaB(accB, P + 1, w2); fmaA(accA, P + 2, w3); }

        if (u < 8) { ldE(tb + offs[0] + rn, P[0], P[1]); }   // unit0 next row

        if (SV == 0) { fmaA(accA, P + 2, w4); fmaB(accB, P + 2, w5); }
        else         { fmaB(accB, P + 2, w4); fmaA(accA, P + 3, w5); }

        if (SV == 0) { fmaA(accA, P + 3, w6); fmaB(accB, P + 3, w7); }
        else         { fmaB(accB, P + 3, w6); fmaA(accA, P + 4, w7); }

        if (u < 8) {
            ldE(tb + offs[1] + rn, P[2], P[3]);              // unit1 next row
            ldE(wr + 80, wp0, wp1);                          // taps 0,1 of u+1
        }

        if (SV == 0) { fmaA(accA, P + 4, w8); }
        else         { fmaB(accB, P + 4, w8); }

        if (u < 8) {                                         // units 2..5(6)
            ldE(tb + offs[2] + rn, P[4],  P[5]);
            ldE(tb + offs[3] + rn, P[6],  P[7]);
            ldE(tb + offs[4] + rn, P[8],  P[9]);
            ldE(tb + offs[5] + rn, P[10], P[11]);
            if (SV == 1) { ldE(tb + offs[6] + rn, P[12], P[13]); }
        }
    }
}

__global__ void __launch_bounds__(256, 3) conv_kernel(
        const float* __restrict__ x, float* __restrict__ out) {
    extern __shared__ float smem[];
    char* buf0 = (char*)smem;
    char* buf1 = buf0 + TILE_B;
    char* wb0  = buf1 + TILE_B;
    char* wb1  = wb0 + WBUF * 8;
    int*  s_ori = (int*)(wb1 + WBUF * 8);

    const int tid = threadIdx.x;
    const int tx  = tid & 7;          // 16-col group
    const int ty  = tid >> 3;         // output row 0..31

    // blockIdx.x = spatial(0..15) * NCHUNK + chunk
    const int chunk = blockIdx.x & (NCHUNK - 1);
    const int sp    = blockIdx.x >> 2;
    const int o  = blockIdx.y;
    const int b  = blockIdx.z;
    const int i0 = (sp >> 1) * TH;
    const int j0 = (sp & 1) * TW;
    const int c0 = chunk * 8;
    const int c1 = min(c0 + 8, NC_);   // 8,8,8,7

    if (tid < NC_) { s_ori[tid] = g_ori[o * NC_ + tid]; }
    __syncthreads();

    const float* __restrict__ xb = x + (size_t)b * NC_ * NXL * NYL;
    const int wdoff = ((tid / WIN_) * WPAD + tid % WIN_) * 8;
    const int half8 = (tx & 1) * 8;
    const int thcu  = tx >> 1;

    // ---- 8B cp.async staging of one channel ----
    auto stage = [&](int c, char* tbuf, char* wbuf) {
        const int ori = s_ori[c];
        const int kx0 = ori >> 8, ky0 = ori & 255;
        const int A   = j0 + (ky0 & ~1) - 8;   // even, 8B-aligned gmem origin
        const int ri0 = i0 + kx0 - 8;
        const float* __restrict__ xc = xb + (size_t)c * (NXL * NYL);
#pragma unroll
        for (int pass = 0; pass < 2; ++pass) {
            if (pass == 1 && ty >= 8) break;
            const int r  = ty + pass * 32;
            const int gi = ri0 + r;
            const bool rowok = (unsigned)gi < NXL;
            const float* grow = xc + (rowok ? gi : 0) * NYL;
            char* rb = tbuf + r * ROWB;
#pragma unroll
            for (int m = 0; m < 8; ++m) {
                const int gcol = A + 2 * (tx + 8 * m);
                const bool ok  = rowok && ((unsigned)gcol < NYL);
                const int dst  = swz_unit(thcu + 4 * m) * 16 + half8;
                __pipeline_memcpy_async(rb + dst,
                                        ok ? grow + gcol : (const float*)xc,
                                        8, ok ? 0 : 8);
            }
            if (tx < 6) {   // tail: dword pairs 64..69
                const int gcol = A + 2 * (tx + 64);
                const bool ok  = rowok && ((unsigned)gcol < NYL);
                const int dst  = swz_unit(thcu + 32) * 16 + half8;
                __pipeline_memcpy_async(rb + dst,
                                        ok ? grow + gcol : (const float*)xc,
                                        8, ok ? 0 : 8);
            }
        }
        if (tid < 81) {
            __pipeline_memcpy_async(wbuf + wdoff,
                                    ((const ull*)g_w2)
                                        + (size_t)(o * NC_ + c) * 81 + tid,
                                    8);
        }
        __pipeline_commit();
    };

    // per-thread swizzled E unit byte offsets (row-independent)
    int offs[7];
#pragma unroll
    for (int e = 0; e < 7; ++e)
        offs[e] = ty * ROWB + swz_unit(4 * tx + e) * 16;

    ull accA[8], accB[9];
#pragma unroll
    for (int j = 0; j < 8; ++j) { accA[j] = 0ull; }
#pragma unroll
    for (int i = 0; i < 9; ++i) { accB[i] = 0ull; }

    stage(c0, buf0, wb0);
    __pipeline_wait_prior(0);
    __syncthreads();

    for (int c = c0; c < c1; ++c) {
        const int k = c - c0;          // local parity
        if (c + 1 < c1)
            stage(c + 1, (k & 1) ? buf0 : buf1, (k & 1) ? wb0 : wb1);

        const char* tb = (k & 1) ? buf1 : buf0;
        const char* wb = (k & 1) ? wb1 : wb0;

        if (s_ori[c] & 1) { channel_math<1>(tb, wb, offs, accA, accB); }
        else              { channel_math<0>(tb, wb, offs, accA, accB); }

        __pipeline_wait_prior(0);
        __syncthreads();
    }

    // ---- epilogue: merge dual-phase accumulators, atomic-add 16 cols ----
    float res[16];
#pragma unroll
    for (int j = 0; j < 8; ++j) {
        float aLo = __uint_as_float((unsigned)(accA[j] & 0xffffffffull));
        float aHi = __uint_as_float((unsigned)(accA[j] >> 32));
        float bHi = __uint_as_float((unsigned)(accB[j] >> 32));
        float bLo = __uint_as_float((unsigned)(accB[j + 1] & 0xffffffffull));
        res[2 * j]     = aLo + bHi;
        res[2 * j + 1] = aHi + bLo;
    }
    float* op = out + ((size_t)(b * NO_ + o) * NXL + (i0 + ty)) * NYL
                    + j0 + tx * 16;
#pragma unroll
    for (int q = 0; q < 16; ++q)
        asm volatile("red.global.add.f32 [%0], %1;"
                     :: "l"(op + q), "f"(res[q]) : "memory");
}

// ---------------------------------------------------------------------------
extern "C" void kernel_launch(void* const* d_in, const int* in_sizes, int n_in,
                              void* d_out, int out_size) {
    const float* x   = (const float*)d_in[0];
    const float* vk  = (const float*)d_in[1];
    const int*   loc = (const int*)d_in[2];
    float* out = (float*)d_out;

    cudaFuncSetAttribute(conv_kernel,
                         cudaFuncAttributeMaxDynamicSharedMemorySize,
                         SMEM_BYTES);

    int n4 = out_size / 4;   // 786432 float4
    zero_out<<<(n4 + 255) / 256, 256>>>((float4*)out, n4);
    prep_all<<<(NG_ * 32 + 255) / 256, 256>>>(vk, loc);

    // x-dim: 16 spatial tiles * 4 channel chunks = 64 -> T = 3072 blocks
    dim3 grid(((NXL / TH) * (NYL / TW)) * NCHUNK, NO_, 16);
    conv_kernel<<<grid, 256, SMEM_BYTES>>>(x, out);
}